// round 1
// baseline (speedup 1.0000x reference)
#include <cuda_runtime.h>

#define BATCH 8
#define TX 128
#define TY 128
#define DD 512
#define HH 512
#define LN_EPS 1e-3f

// Scratch (allocation-free rule: __device__ globals)
__device__ float g_Wc[BATCH * TX * HH];  // context @ Wa + bWa
__device__ float g_Ux[BATCH * TY * HH];  // x @ Ua + bUa

// ---------------------------------------------------------------------------
// Fast math helpers (approx error ~1e-7 absolute; safe vs 1e-3 rel_err gate)
// ---------------------------------------------------------------------------
__device__ __forceinline__ float fast_ex2(float x) {
    float r; asm("ex2.approx.f32 %0, %1;" : "=f"(r) : "f"(x)); return r;
}
__device__ __forceinline__ float fast_rcp(float x) {
    float r; asm("rcp.approx.f32 %0, %1;" : "=f"(r) : "f"(x)); return r;
}
// tanh(x) = 1 - 2/(exp(2x)+1); exp(2x) = 2^(2*log2(e)*x)
__device__ __forceinline__ float fast_tanh(float x) {
    float e = fast_ex2(x * 2.885390081777927f);   // 2*log2(e)
    float r = fast_rcp(e + 1.0f);
    return fmaf(-2.0f, r, 1.0f);
}
__device__ __forceinline__ float fast_exp(float x) {
    return fast_ex2(x * 1.4426950408889634f);
}

// ---------------------------------------------------------------------------
// GEMM: C[M,N] = A[M,K] @ W[K,N] + bias   (M=1024, K=N=512)
// blockIdx.z == 0: Wc = context @ Wa + bWa
// blockIdx.z == 1: Ux = x       @ Ua + bUa
// 64x64 tile, 256 threads, 4x4 per thread, K-tile 16
// ---------------------------------------------------------------------------
__global__ __launch_bounds__(256)
void gemm_bias_kernel(const float* __restrict__ ctx,
                      const float* __restrict__ xin,
                      const float* __restrict__ Wa,
                      const float* __restrict__ bWa,
                      const float* __restrict__ Ua,
                      const float* __restrict__ bUa)
{
    const int K = DD, N = HH;
    const float* A; const float* W; const float* bias; float* C;
    if (blockIdx.z == 0) { A = ctx; W = Wa; bias = bWa; C = g_Wc; }
    else                 { A = xin; W = Ua; bias = bUa; C = g_Ux; }

    __shared__ __align__(16) float As[16][68];  // [k][m] transposed
    __shared__ __align__(16) float Bs[16][68];  // [k][n]

    const int bm = blockIdx.y * 64;
    const int bn = blockIdx.x * 64;
    const int tid = threadIdx.x;
    const int tr = tid / 16;          // 0..15  -> 4 rows each
    const int tc = tid % 16;          // 0..15  -> 4 cols each

    const int lrowA = tid >> 2;       // 0..63
    const int lqA   = tid & 3;        // float4 slot along K
    const int lrowB = tid >> 4;       // 0..15 (k)
    const int lcB   = tid & 15;       // float4 slot along N

    float acc[4][4] = {};

    for (int k0 = 0; k0 < K; k0 += 16) {
        float4 a4 = *(const float4*)(A + (size_t)(bm + lrowA) * K + k0 + lqA * 4);
        As[lqA * 4 + 0][lrowA] = a4.x;
        As[lqA * 4 + 1][lrowA] = a4.y;
        As[lqA * 4 + 2][lrowA] = a4.z;
        As[lqA * 4 + 3][lrowA] = a4.w;
        float4 b4 = *(const float4*)(W + (size_t)(k0 + lrowB) * N + bn + lcB * 4);
        *(float4*)&Bs[lrowB][lcB * 4] = b4;
        __syncthreads();

        #pragma unroll
        for (int kk = 0; kk < 16; ++kk) {
            float4 av = *(const float4*)&As[kk][tr * 4];
            float4 bv = *(const float4*)&Bs[kk][tc * 4];
            float a_[4] = {av.x, av.y, av.z, av.w};
            float b_[4] = {bv.x, bv.y, bv.z, bv.w};
            #pragma unroll
            for (int i = 0; i < 4; ++i)
                #pragma unroll
                for (int j = 0; j < 4; ++j)
                    acc[i][j] = fmaf(a_[i], b_[j], acc[i][j]);
        }
        __syncthreads();
    }

    const float4 bias4 = *(const float4*)(bias + bn + tc * 4);
    const float bb[4] = {bias4.x, bias4.y, bias4.z, bias4.w};
    #pragma unroll
    for (int i = 0; i < 4; ++i) {
        const int row = bm + tr * 4 + i;
        float4 o;
        o.x = acc[i][0] + bb[0];
        o.y = acc[i][1] + bb[1];
        o.z = acc[i][2] + bb[2];
        o.w = acc[i][3] + bb[3];
        *(float4*)(C + (size_t)row * N + bn + tc * 4) = o;
    }
}

// ---------------------------------------------------------------------------
// Fused attention: one block per (b, ty). 512 threads (16 warps).
// Phase A: scores[tx] = sum_h tanh(Wc[b,tx,h] + Ux[b,ty,h]) * Va[h]
// Phase B: softmax over tx (warp 0)
// Phase C: cv[d] = sum_tx attn[tx] * context[b,tx,d]   (thread d)
// Phase D: LayerNorm(cv)*gamma+beta + x  -> out
// ---------------------------------------------------------------------------
__global__ __launch_bounds__(512)
void attn_fused_kernel(const float* __restrict__ ctx,
                       const float* __restrict__ xin,
                       const float* __restrict__ Va,
                       const float* __restrict__ bVa,
                       const float* __restrict__ gamma,
                       const float* __restrict__ beta,
                       float* __restrict__ out)
{
    const int b  = blockIdx.y;
    const int ty = blockIdx.x;
    const int tid  = threadIdx.x;
    const int lane = tid & 31;
    const int wid  = tid >> 5;        // 0..15

    __shared__ float sUx[HH];
    __shared__ float sVa[HH];
    __shared__ float sAttn[TX];
    __shared__ float sRed[16];

    const float* uxrow = g_Ux + ((size_t)b * TY + ty) * HH;
    for (int i = tid; i < HH; i += 512) { sUx[i] = uxrow[i]; sVa[i] = Va[i]; }
    __syncthreads();

    // --- Phase A: scores ---
    const float* WcB = g_Wc + (size_t)b * TX * HH;
    #pragma unroll
    for (int r = 0; r < 8; ++r) {
        const int tx = wid + 16 * r;
        const float* wcrow = WcB + (size_t)tx * HH;
        float acc = 0.f;
        #pragma unroll
        for (int i = 0; i < 16; ++i) {
            const int h = lane + 32 * i;
            const float s = wcrow[h] + sUx[h];
            acc = fmaf(fast_tanh(s), sVa[h], acc);
        }
        #pragma unroll
        for (int o = 16; o; o >>= 1)
            acc += __shfl_xor_sync(0xffffffffu, acc, o);
        if (lane == 0) sAttn[tx] = acc;  // raw score (bVa shift is softmax-invariant)
    }
    __syncthreads();

    // --- Phase B: softmax over 128 scores (warp 0) ---
    if (wid == 0) {
        float s0 = sAttn[lane], s1 = sAttn[lane + 32];
        float s2 = sAttn[lane + 64], s3 = sAttn[lane + 96];
        float m = fmaxf(fmaxf(s0, s1), fmaxf(s2, s3));
        #pragma unroll
        for (int o = 16; o; o >>= 1)
            m = fmaxf(m, __shfl_xor_sync(0xffffffffu, m, o));
        float e0 = fast_exp(s0 - m), e1 = fast_exp(s1 - m);
        float e2 = fast_exp(s2 - m), e3 = fast_exp(s3 - m);
        float sum = (e0 + e1) + (e2 + e3);
        #pragma unroll
        for (int o = 16; o; o >>= 1)
            sum += __shfl_xor_sync(0xffffffffu, sum, o);
        const float inv = fast_rcp(sum);
        sAttn[lane]      = e0 * inv;
        sAttn[lane + 32] = e1 * inv;
        sAttn[lane + 64] = e2 * inv;
        sAttn[lane + 96] = e3 * inv;
    }
    __syncthreads();

    // --- Phase C: context vector, one d per thread ---
    const int d = tid;
    const float* ctxB = ctx + (size_t)b * TX * DD;
    float cv = 0.f;
    #pragma unroll 8
    for (int tx = 0; tx < TX; ++tx)
        cv = fmaf(sAttn[tx], ctxB[(size_t)tx * DD + d], cv);

    // --- Phase D: LayerNorm + residual ---
    // mean
    float v = cv;
    #pragma unroll
    for (int o = 16; o; o >>= 1) v += __shfl_xor_sync(0xffffffffu, v, o);
    if (lane == 0) sRed[wid] = v;
    __syncthreads();
    if (wid == 0) {
        float t = (lane < 16) ? sRed[lane] : 0.f;
        #pragma unroll
        for (int o = 8; o; o >>= 1) t += __shfl_xor_sync(0xffffffffu, t, o);
        if (lane == 0) sRed[0] = t;
    }
    __syncthreads();
    const float mean = sRed[0] * (1.0f / HH);
    __syncthreads();

    const float diff = cv - mean;
    float v2 = diff * diff;
    #pragma unroll
    for (int o = 16; o; o >>= 1) v2 += __shfl_xor_sync(0xffffffffu, v2, o);
    if (lane == 0) sRed[wid] = v2;
    __syncthreads();
    if (wid == 0) {
        float t = (lane < 16) ? sRed[lane] : 0.f;
        #pragma unroll
        for (int o = 8; o; o >>= 1) t += __shfl_xor_sync(0xffffffffu, t, o);
        if (lane == 0) sRed[0] = t;
    }
    __syncthreads();
    const float var = sRed[0] * (1.0f / HH);

    const float inv_std = rsqrtf(var + LN_EPS);
    const size_t oidx = ((size_t)b * TY + ty) * DD + d;
    out[oidx] = fmaf(diff * inv_std, gamma[d], beta[d]) + xin[oidx];
}

// ---------------------------------------------------------------------------
extern "C" void kernel_launch(void* const* d_in, const int* in_sizes, int n_in,
                              void* d_out, int out_size)
{
    const float* ctx   = (const float*)d_in[0];
    const float* xin   = (const float*)d_in[1];
    const float* Wa    = (const float*)d_in[2];
    const float* bWa   = (const float*)d_in[3];
    const float* Ua    = (const float*)d_in[4];
    const float* bUa   = (const float*)d_in[5];
    const float* Va    = (const float*)d_in[6];
    const float* bVa   = (const float*)d_in[7];
    const float* gamma = (const float*)d_in[8];
    const float* beta  = (const float*)d_in[9];
    float* out = (float*)d_out;

    dim3 ggrid(HH / 64, (BATCH * TX) / 64, 2);   // (8, 16, 2)
    gemm_bias_kernel<<<ggrid, 256>>>(ctx, xin, Wa, bWa, Ua, bUa);

    dim3 agrid(TY, BATCH);                       // (128, 8)
    attn_fused_kernel<<<agrid, 512>>>(ctx, xin, Va, bVa, gamma, beta, out);
}

// round 2
// speedup vs baseline: 1.0461x; 1.0461x over previous
#include <cuda_runtime.h>

#define BATCH 8
#define TX 128
#define TY 128
#define DD 512
#define HH 512
#define LN_EPS 1e-3f

// Scratch (allocation-free rule: __device__ globals)
__device__ float g_Wc[BATCH * TX * HH];  // context @ Wa + bWa
__device__ float g_Ux[BATCH * TY * HH];  // x @ Ua + bUa

// ---------------------------------------------------------------------------
// Fast math helpers
// ---------------------------------------------------------------------------
__device__ __forceinline__ float fast_ex2(float x) {
    float r; asm("ex2.approx.f32 %0, %1;" : "=f"(r) : "f"(x)); return r;
}
__device__ __forceinline__ float fast_rcp(float x) {
    float r; asm("rcp.approx.f32 %0, %1;" : "=f"(r) : "f"(x)); return r;
}
// Native single-MUFU tanh (sm_75+). ~5e-4 abs err worst case; averages out
// over the 512-wide h-reduction against |Va|~0.044 -> final err ~1e-5.
__device__ __forceinline__ float fast_tanh(float x) {
    float r; asm("tanh.approx.f32 %0, %1;" : "=f"(r) : "f"(x)); return r;
}
__device__ __forceinline__ float fast_exp(float x) {
    return fast_ex2(x * 1.4426950408889634f);
}

// ---------------------------------------------------------------------------
// GEMM: C[M,N] = A[M,K] @ W[K,N] + bias   (M=1024, K=N=512)
// blockIdx.z == 0: Wc = context @ Wa + bWa
// blockIdx.z == 1: Ux = x       @ Ua + bUa
// 64x64 tile, 256 threads, 4x4 per thread, K-tile 16 (~fp32 roofline already)
// ---------------------------------------------------------------------------
__global__ __launch_bounds__(256)
void gemm_bias_kernel(const float* __restrict__ ctx,
                      const float* __restrict__ xin,
                      const float* __restrict__ Wa,
                      const float* __restrict__ bWa,
                      const float* __restrict__ Ua,
                      const float* __restrict__ bUa)
{
    const int K = DD, N = HH;
    const float* A; const float* W; const float* bias; float* C;
    if (blockIdx.z == 0) { A = ctx; W = Wa; bias = bWa; C = g_Wc; }
    else                 { A = xin; W = Ua; bias = bUa; C = g_Ux; }

    __shared__ __align__(16) float As[16][68];  // [k][m] transposed
    __shared__ __align__(16) float Bs[16][68];  // [k][n]

    const int bm = blockIdx.y * 64;
    const int bn = blockIdx.x * 64;
    const int tid = threadIdx.x;
    const int tr = tid / 16;
    const int tc = tid % 16;

    const int lrowA = tid >> 2;
    const int lqA   = tid & 3;
    const int lrowB = tid >> 4;
    const int lcB   = tid & 15;

    float acc[4][4] = {};

    for (int k0 = 0; k0 < K; k0 += 16) {
        float4 a4 = *(const float4*)(A + (size_t)(bm + lrowA) * K + k0 + lqA * 4);
        As[lqA * 4 + 0][lrowA] = a4.x;
        As[lqA * 4 + 1][lrowA] = a4.y;
        As[lqA * 4 + 2][lrowA] = a4.z;
        As[lqA * 4 + 3][lrowA] = a4.w;
        float4 b4 = *(const float4*)(W + (size_t)(k0 + lrowB) * N + bn + lcB * 4);
        *(float4*)&Bs[lrowB][lcB * 4] = b4;
        __syncthreads();

        #pragma unroll
        for (int kk = 0; kk < 16; ++kk) {
            float4 av = *(const float4*)&As[kk][tr * 4];
            float4 bv = *(const float4*)&Bs[kk][tc * 4];
            float a_[4] = {av.x, av.y, av.z, av.w};
            float b_[4] = {bv.x, bv.y, bv.z, bv.w};
            #pragma unroll
            for (int i = 0; i < 4; ++i)
                #pragma unroll
                for (int j = 0; j < 4; ++j)
                    acc[i][j] = fmaf(a_[i], b_[j], acc[i][j]);
        }
        __syncthreads();
    }

    const float4 bias4 = *(const float4*)(bias + bn + tc * 4);
    const float bb[4] = {bias4.x, bias4.y, bias4.z, bias4.w};
    #pragma unroll
    for (int i = 0; i < 4; ++i) {
        const int row = bm + tr * 4 + i;
        float4 o;
        o.x = acc[i][0] + bb[0];
        o.y = acc[i][1] + bb[1];
        o.z = acc[i][2] + bb[2];
        o.w = acc[i][3] + bb[3];
        *(float4*)(C + (size_t)row * N + bn + tc * 4) = o;
    }
}

// ---------------------------------------------------------------------------
// Fused attention: one block per (b, ty). 512 threads (16 warps).
// Phase A: scores[tx] = sum_h tanh(Wc[b,tx,h] + Ux[b,ty,h]) * Va[h]  (float4)
// Phase B: softmax over tx (warp 0)
// Phase C: cv[d] = sum_tx attn[tx] * context[b,tx,d]  (4 groups x 128 thr, float4)
// Phase D: LayerNorm(cv)*gamma+beta + x  -> out
// ---------------------------------------------------------------------------
__global__ __launch_bounds__(512)
void attn_fused_kernel(const float* __restrict__ ctx,
                       const float* __restrict__ xin,
                       const float* __restrict__ Va,
                       const float* __restrict__ bVa,
                       const float* __restrict__ gamma,
                       const float* __restrict__ beta,
                       float* __restrict__ out)
{
    const int b  = blockIdx.y;
    const int ty = blockIdx.x;
    const int tid  = threadIdx.x;
    const int lane = tid & 31;
    const int wid  = tid >> 5;        // 0..15

    __shared__ __align__(16) float sUx[HH];
    __shared__ __align__(16) float sVa[HH];
    __shared__ __align__(16) float sCv[4][DD / 4][4];  // [group][d4][comp] = 8KB
    __shared__ float sAttn[TX];
    __shared__ float sRed[16];

    // Load Ux row + Va into shared (float4)
    {
        const float4* uxrow4 = (const float4*)(g_Ux + ((size_t)b * TY + ty) * HH);
        const float4* va4    = (const float4*)Va;
        float4* sU4 = (float4*)sUx;
        float4* sV4 = (float4*)sVa;
        for (int i = tid; i < HH / 4; i += 512) { sU4[i] = uxrow4[i]; sV4[i] = va4[i]; }
    }
    __syncthreads();

    // --- Phase A: scores (each warp: 8 tx rows; lane covers 4 h per iter) ---
    const float* WcB = g_Wc + (size_t)b * TX * HH;
    const float4* sU4 = (const float4*)sUx;
    const float4* sV4 = (const float4*)sVa;
    #pragma unroll
    for (int r = 0; r < 8; ++r) {
        const int tx = wid + 16 * r;
        const float4* wcrow4 = (const float4*)(WcB + (size_t)tx * HH);
        float acc = 0.f;
        #pragma unroll
        for (int i = 0; i < 4; ++i) {
            const int q = lane + 32 * i;   // float4 index 0..127
            float4 w4 = wcrow4[q];
            float4 u4 = sU4[q];
            float4 v4 = sV4[q];
            acc = fmaf(fast_tanh(w4.x + u4.x), v4.x, acc);
            acc = fmaf(fast_tanh(w4.y + u4.y), v4.y, acc);
            acc = fmaf(fast_tanh(w4.z + u4.z), v4.z, acc);
            acc = fmaf(fast_tanh(w4.w + u4.w), v4.w, acc);
        }
        #pragma unroll
        for (int o = 16; o; o >>= 1)
            acc += __shfl_xor_sync(0xffffffffu, acc, o);
        if (lane == 0) sAttn[tx] = acc;   // raw score (bVa shift softmax-invariant)
    }
    __syncthreads();

    // --- Phase B: softmax over 128 scores (warp 0) ---
    if (wid == 0) {
        float s0 = sAttn[lane], s1 = sAttn[lane + 32];
        float s2 = sAttn[lane + 64], s3 = sAttn[lane + 96];
        float m = fmaxf(fmaxf(s0, s1), fmaxf(s2, s3));
        #pragma unroll
        for (int o = 16; o; o >>= 1)
            m = fmaxf(m, __shfl_xor_sync(0xffffffffu, m, o));
        float e0 = fast_exp(s0 - m), e1 = fast_exp(s1 - m);
        float e2 = fast_exp(s2 - m), e3 = fast_exp(s3 - m);
        float sum = (e0 + e1) + (e2 + e3);
        #pragma unroll
        for (int o = 16; o; o >>= 1)
            sum += __shfl_xor_sync(0xffffffffu, sum, o);
        const float inv = fast_rcp(sum);
        sAttn[lane]      = e0 * inv;
        sAttn[lane + 32] = e1 * inv;
        sAttn[lane + 64] = e2 * inv;
        sAttn[lane + 96] = e3 * inv;
    }
    __syncthreads();

    // --- Phase C: cv via 4 groups of 128 threads, float4 over d ---
    {
        const int g  = tid >> 7;        // group 0..3 -> tx chunk
        const int lt = tid & 127;       // d-quad index (d = 4*lt .. 4*lt+3)
        const float4* ctxB4 = (const float4*)(ctx + (size_t)b * TX * DD);
        float4 cv4 = make_float4(0.f, 0.f, 0.f, 0.f);
        #pragma unroll 8
        for (int t = 0; t < 32; ++t) {
            const int tx = g * 32 + t;
            const float a = sAttn[tx];
            const float4 c4 = ctxB4[(size_t)tx * (DD / 4) + lt];
            cv4.x = fmaf(a, c4.x, cv4.x);
            cv4.y = fmaf(a, c4.y, cv4.y);
            cv4.z = fmaf(a, c4.z, cv4.z);
            cv4.w = fmaf(a, c4.w, cv4.w);
        }
        *(float4*)&sCv[g][lt][0] = cv4;
    }
    __syncthreads();

    // Final cv for d = tid
    const int d = tid;
    const int dq = d >> 2, dc = d & 3;
    const float cv = sCv[0][dq][dc] + sCv[1][dq][dc] + sCv[2][dq][dc] + sCv[3][dq][dc];

    // --- Phase D: LayerNorm + residual ---
    float v = cv;
    #pragma unroll
    for (int o = 16; o; o >>= 1) v += __shfl_xor_sync(0xffffffffu, v, o);
    if (lane == 0) sRed[wid] = v;
    __syncthreads();
    if (wid == 0) {
        float t = (lane < 16) ? sRed[lane] : 0.f;
        #pragma unroll
        for (int o = 8; o; o >>= 1) t += __shfl_xor_sync(0xffffffffu, t, o);
        if (lane == 0) sRed[0] = t;
    }
    __syncthreads();
    const float mean = sRed[0] * (1.0f / HH);
    __syncthreads();

    const float diff = cv - mean;
    float v2 = diff * diff;
    #pragma unroll
    for (int o = 16; o; o >>= 1) v2 += __shfl_xor_sync(0xffffffffu, v2, o);
    if (lane == 0) sRed[wid] = v2;
    __syncthreads();
    if (wid == 0) {
        float t = (lane < 16) ? sRed[lane] : 0.f;
        #pragma unroll
        for (int o = 8; o; o >>= 1) t += __shfl_xor_sync(0xffffffffu, t, o);
        if (lane == 0) sRed[0] = t;
    }
    __syncthreads();
    const float var = sRed[0] * (1.0f / HH);

    const float inv_std = rsqrtf(var + LN_EPS);
    const size_t oidx = ((size_t)b * TY + ty) * DD + d;
    out[oidx] = fmaf(diff * inv_std, gamma[d], beta[d]) + xin[oidx];
}

// ---------------------------------------------------------------------------
extern "C" void kernel_launch(void* const* d_in, const int* in_sizes, int n_in,
                              void* d_out, int out_size)
{
    const float* ctx   = (const float*)d_in[0];
    const float* xin   = (const float*)d_in[1];
    const float* Wa    = (const float*)d_in[2];
    const float* bWa   = (const float*)d_in[3];
    const float* Ua    = (const float*)d_in[4];
    const float* bUa   = (const float*)d_in[5];
    const float* Va    = (const float*)d_in[6];
    const float* bVa   = (const float*)d_in[7];
    const float* gamma = (const float*)d_in[8];
    const float* beta  = (const float*)d_in[9];
    float* out = (float*)d_out;

    dim3 ggrid(HH / 64, (BATCH * TX) / 64, 2);   // (8, 16, 2)
    gemm_bias_kernel<<<ggrid, 256>>>(ctx, xin, Wa, bWa, Ua, bUa);

    dim3 agrid(TY, BATCH);                       // (128, 8)
    attn_fused_kernel<<<agrid, 512>>>(ctx, xin, Va, bVa, gamma, beta, out);
}

// round 3
// speedup vs baseline: 1.1820x; 1.1299x over previous
#include <cuda_runtime.h>

#define BATCH 8
#define TX 128
#define TY 128
#define DD 512
#define HH 512
#define LN_EPS 1e-3f

// Scratch (allocation-free rule: __device__ globals)
__device__ float g_Wc[BATCH * TX * HH];  // context @ Wa + bWa
__device__ float g_Ux[BATCH * TY * HH];  // x @ Ua + bUa

// ---------------------------------------------------------------------------
// Fast math helpers
// ---------------------------------------------------------------------------
__device__ __forceinline__ float fast_ex2(float x) {
    float r; asm("ex2.approx.f32 %0, %1;" : "=f"(r) : "f"(x)); return r;
}
__device__ __forceinline__ float fast_rcp(float x) {
    float r; asm("rcp.approx.f32 %0, %1;" : "=f"(r) : "f"(x)); return r;
}
__device__ __forceinline__ float fast_tanh(float x) {
    float r; asm("tanh.approx.f32 %0, %1;" : "=f"(r) : "f"(x)); return r;
}
__device__ __forceinline__ float fast_exp(float x) {
    return fast_ex2(x * 1.4426950408889634f);
}

// ---------------------------------------------------------------------------
// GEMM: C[M,N] = A[M,K] @ W[K,N] + bias   (M=1024, K=N=512)
// blockIdx.z == 0: Wc = context @ Wa + bWa
// blockIdx.z == 1: Ux = x       @ Ua + bUa
// ---------------------------------------------------------------------------
__global__ __launch_bounds__(256)
void gemm_bias_kernel(const float* __restrict__ ctx,
                      const float* __restrict__ xin,
                      const float* __restrict__ Wa,
                      const float* __restrict__ bWa,
                      const float* __restrict__ Ua,
                      const float* __restrict__ bUa)
{
    const int K = DD, N = HH;
    const float* A; const float* W; const float* bias; float* C;
    if (blockIdx.z == 0) { A = ctx; W = Wa; bias = bWa; C = g_Wc; }
    else                 { A = xin; W = Ua; bias = bUa; C = g_Ux; }

    __shared__ __align__(16) float As[16][68];  // [k][m] transposed
    __shared__ __align__(16) float Bs[16][68];  // [k][n]

    const int bm = blockIdx.y * 64;
    const int bn = blockIdx.x * 64;
    const int tid = threadIdx.x;
    const int tr = tid / 16;
    const int tc = tid % 16;

    const int lrowA = tid >> 2;
    const int lqA   = tid & 3;
    const int lrowB = tid >> 4;
    const int lcB   = tid & 15;

    float acc[4][4] = {};

    for (int k0 = 0; k0 < K; k0 += 16) {
        float4 a4 = *(const float4*)(A + (size_t)(bm + lrowA) * K + k0 + lqA * 4);
        As[lqA * 4 + 0][lrowA] = a4.x;
        As[lqA * 4 + 1][lrowA] = a4.y;
        As[lqA * 4 + 2][lrowA] = a4.z;
        As[lqA * 4 + 3][lrowA] = a4.w;
        float4 b4 = *(const float4*)(W + (size_t)(k0 + lrowB) * N + bn + lcB * 4);
        *(float4*)&Bs[lrowB][lcB * 4] = b4;
        __syncthreads();

        #pragma unroll
        for (int kk = 0; kk < 16; ++kk) {
            float4 av = *(const float4*)&As[kk][tr * 4];
            float4 bv = *(const float4*)&Bs[kk][tc * 4];
            float a_[4] = {av.x, av.y, av.z, av.w};
            float b_[4] = {bv.x, bv.y, bv.z, bv.w};
            #pragma unroll
            for (int i = 0; i < 4; ++i)
                #pragma unroll
                for (int j = 0; j < 4; ++j)
                    acc[i][j] = fmaf(a_[i], b_[j], acc[i][j]);
        }
        __syncthreads();
    }

    const float4 bias4 = *(const float4*)(bias + bn + tc * 4);
    const float bb[4] = {bias4.x, bias4.y, bias4.z, bias4.w};
    #pragma unroll
    for (int i = 0; i < 4; ++i) {
        const int row = bm + tr * 4 + i;
        float4 o;
        o.x = acc[i][0] + bb[0];
        o.y = acc[i][1] + bb[1];
        o.z = acc[i][2] + bb[2];
        o.w = acc[i][3] + bb[3];
        *(float4*)(C + (size_t)row * N + bn + tc * 4) = o;
    }
}

// ---------------------------------------------------------------------------
// Fused attention: one block per (b, ty-pair). 512 threads, 2 blocks/SM.
// Each block handles ty0 = 2*blockIdx.x and ty0+1, amortizing Wc loads 2x.
// ---------------------------------------------------------------------------
__global__ __launch_bounds__(512, 2)
void attn_fused_kernel(const float* __restrict__ ctx,
                       const float* __restrict__ xin,
                       const float* __restrict__ Va,
                       const float* __restrict__ bVa,
                       const float* __restrict__ gamma,
                       const float* __restrict__ beta,
                       float* __restrict__ out)
{
    const int b   = blockIdx.y;
    const int ty0 = blockIdx.x * 2;
    const int tid  = threadIdx.x;
    const int lane = tid & 31;
    const int wid  = tid >> 5;        // 0..15

    __shared__ __align__(16) float sUx[2][HH];
    __shared__ __align__(16) float sVa[HH];
    __shared__ __align__(16) float sCv[4][DD / 4][4];  // 8KB, reused per ty
    __shared__ float sAttn[2][TX];
    __shared__ float sRed[2][16];

    // Load 2 Ux rows + Va into shared (float4)
    {
        const float4* uxrow4 = (const float4*)(g_Ux + ((size_t)b * TY + ty0) * HH);
        const float4* va4    = (const float4*)Va;
        float4* sU4 = (float4*)sUx[0];   // 2*HH contiguous
        float4* sV4 = (float4*)sVa;
        for (int i = tid; i < 2 * HH / 4; i += 512) sU4[i] = uxrow4[i];
        for (int i = tid; i < HH / 4; i += 512) sV4[i] = va4[i];
    }
    __syncthreads();

    // --- Phase A: scores for both ty rows; each Wc load feeds 2 tanh-chains ---
    const float* WcB = g_Wc + (size_t)b * TX * HH;
    const float4* sU4a = (const float4*)sUx[0];
    const float4* sU4b = (const float4*)sUx[1];
    const float4* sV4  = (const float4*)sVa;
    #pragma unroll
    for (int r = 0; r < 8; ++r) {
        const int tx = wid + 16 * r;
        const float4* wcrow4 = (const float4*)(WcB + (size_t)tx * HH);
        float acc0 = 0.f, acc1 = 0.f;
        #pragma unroll
        for (int i = 0; i < 4; ++i) {
            const int q = lane + 32 * i;   // float4 index 0..127
            float4 w4 = wcrow4[q];
            float4 v4 = sV4[q];
            float4 ua = sU4a[q];
            acc0 = fmaf(fast_tanh(w4.x + ua.x), v4.x, acc0);
            acc0 = fmaf(fast_tanh(w4.y + ua.y), v4.y, acc0);
            acc0 = fmaf(fast_tanh(w4.z + ua.z), v4.z, acc0);
            acc0 = fmaf(fast_tanh(w4.w + ua.w), v4.w, acc0);
            float4 ub = sU4b[q];
            acc1 = fmaf(fast_tanh(w4.x + ub.x), v4.x, acc1);
            acc1 = fmaf(fast_tanh(w4.y + ub.y), v4.y, acc1);
            acc1 = fmaf(fast_tanh(w4.z + ub.z), v4.z, acc1);
            acc1 = fmaf(fast_tanh(w4.w + ub.w), v4.w, acc1);
        }
        #pragma unroll
        for (int o = 16; o; o >>= 1) {
            acc0 += __shfl_xor_sync(0xffffffffu, acc0, o);
            acc1 += __shfl_xor_sync(0xffffffffu, acc1, o);
        }
        if (lane == 0) { sAttn[0][tx] = acc0; sAttn[1][tx] = acc1; }
    }
    __syncthreads();

    // --- Phase B: softmax; warp 0 handles ty0, warp 1 handles ty0+1 ---
    if (wid < 2) {
        float* row = sAttn[wid];
        float s0 = row[lane], s1 = row[lane + 32];
        float s2 = row[lane + 64], s3 = row[lane + 96];
        float m = fmaxf(fmaxf(s0, s1), fmaxf(s2, s3));
        #pragma unroll
        for (int o = 16; o; o >>= 1)
            m = fmaxf(m, __shfl_xor_sync(0xffffffffu, m, o));
        float e0 = fast_exp(s0 - m), e1 = fast_exp(s1 - m);
        float e2 = fast_exp(s2 - m), e3 = fast_exp(s3 - m);
        float sum = (e0 + e1) + (e2 + e3);
        #pragma unroll
        for (int o = 16; o; o >>= 1)
            sum += __shfl_xor_sync(0xffffffffu, sum, o);
        const float inv = fast_rcp(sum);
        row[lane]      = e0 * inv;
        row[lane + 32] = e1 * inv;
        row[lane + 64] = e2 * inv;
        row[lane + 96] = e3 * inv;
    }
    __syncthreads();

    // --- Phases C+D per ty row ---
    const float4* ctxB4 = (const float4*)(ctx + (size_t)b * TX * DD);
    const int g  = tid >> 7;        // group 0..3 -> tx chunk
    const int lt = tid & 127;       // d-quad index
    const int d  = tid;
    const int dq = d >> 2, dc = d & 3;

    #pragma unroll
    for (int j = 0; j < 2; ++j) {
        // Phase C: cv partial sums, 4 groups x 128 threads, float4 over d
        float4 cv4 = make_float4(0.f, 0.f, 0.f, 0.f);
        const float* attn = sAttn[j];
        #pragma unroll 8
        for (int t = 0; t < 32; ++t) {
            const int tx = g * 32 + t;
            const float a = attn[tx];
            const float4 c4 = ctxB4[(size_t)tx * (DD / 4) + lt];
            cv4.x = fmaf(a, c4.x, cv4.x);
            cv4.y = fmaf(a, c4.y, cv4.y);
            cv4.z = fmaf(a, c4.z, cv4.z);
            cv4.w = fmaf(a, c4.w, cv4.w);
        }
        *(float4*)&sCv[g][lt][0] = cv4;
        __syncthreads();

        const float cv = sCv[0][dq][dc] + sCv[1][dq][dc] + sCv[2][dq][dc] + sCv[3][dq][dc];

        // Phase D: LayerNorm + residual
        float v = cv;
        #pragma unroll
        for (int o = 16; o; o >>= 1) v += __shfl_xor_sync(0xffffffffu, v, o);
        if (lane == 0) sRed[j][wid] = v;
        __syncthreads();
        if (wid == 0) {
            float t = (lane < 16) ? sRed[j][lane] : 0.f;
            #pragma unroll
            for (int o = 8; o; o >>= 1) t += __shfl_xor_sync(0xffffffffu, t, o);
            if (lane == 0) sRed[j][0] = t;
        }
        __syncthreads();
        const float mean = sRed[j][0] * (1.0f / HH);
        __syncthreads();

        const float diff = cv - mean;
        float v2 = diff * diff;
        #pragma unroll
        for (int o = 16; o; o >>= 1) v2 += __shfl_xor_sync(0xffffffffu, v2, o);
        if (lane == 0) sRed[j][wid] = v2;
        __syncthreads();
        if (wid == 0) {
            float t = (lane < 16) ? sRed[j][lane] : 0.f;
            #pragma unroll
            for (int o = 8; o; o >>= 1) t += __shfl_xor_sync(0xffffffffu, t, o);
            if (lane == 0) sRed[j][0] = t;
        }
        __syncthreads();
        const float var = sRed[j][0] * (1.0f / HH);

        const float inv_std = rsqrtf(var + LN_EPS);
        const size_t oidx = ((size_t)b * TY + ty0 + j) * DD + d;
        out[oidx] = fmaf(diff * inv_std, gamma[d], beta[d]) + xin[oidx];
        __syncthreads();   // sCv / sRed reuse across j
    }
}

// ---------------------------------------------------------------------------
extern "C" void kernel_launch(void* const* d_in, const int* in_sizes, int n_in,
                              void* d_out, int out_size)
{
    const float* ctx   = (const float*)d_in[0];
    const float* xin   = (const float*)d_in[1];
    const float* Wa    = (const float*)d_in[2];
    const float* bWa   = (const float*)d_in[3];
    const float* Ua    = (const float*)d_in[4];
    const float* bUa   = (const float*)d_in[5];
    const float* Va    = (const float*)d_in[6];
    const float* bVa   = (const float*)d_in[7];
    const float* gamma = (const float*)d_in[8];
    const float* beta  = (const float*)d_in[9];
    float* out = (float*)d_out;

    dim3 ggrid(HH / 64, (BATCH * TX) / 64, 2);   // (8, 16, 2)
    gemm_bias_kernel<<<ggrid, 256>>>(ctx, xin, Wa, bWa, Ua, bUa);

    dim3 agrid(TY / 2, BATCH);                   // (64, 8)
    attn_fused_kernel<<<agrid, 512>>>(ctx, xin, Va, bVa, gamma, beta, out);
}